// round 15
// baseline (speedup 1.0000x reference)
#include <cuda_runtime.h>
#include <cuda_bf16.h>
#include <math.h>
#include <stdint.h>

#define BDIM  8
#define C2D   256
#define NTOK  1024
#define NHEAD 8
#define DHEAD 32
#define KCL   3
#define QKSCALE 0.17677669529663687f
#define EXPSC  (0.17677669529663687f * 1.4426950408889634f)

// ---------------- scratch ----------------
__device__ float g_xf  [BDIM * C2D * NTOK];
__device__ float g_prob[BDIM * KCL * NTOK];
__device__ __nv_bfloat16 g_xft [BDIM * NTOK * C2D];
__device__ __nv_bfloat16 g_qh  [BDIM * NHEAD * NTOK * DHEAD];
__device__ __nv_bfloat16 g_kh  [BDIM * NHEAD * NTOK * DHEAD];
__device__ __nv_bfloat16 g_vh  [BDIM * NHEAD * DHEAD * NTOK];
__device__ __nv_bfloat16 g_attt[BDIM * NTOK * C2D];

// ---------------- helpers ----------------
__device__ __forceinline__ uint32_t smem_u32(const void* p) {
    uint32_t a;
    asm("{ .reg .u64 t; cvta.to.shared.u64 t, %1; cvt.u32.u64 %0, t; }" : "=r"(a) : "l"(p));
    return a;
}
__device__ __forceinline__ void mma16816(float* d,
    uint32_t a0, uint32_t a1, uint32_t a2, uint32_t a3,
    uint32_t b0, uint32_t b1)
{
    asm volatile(
        "mma.sync.aligned.m16n8k16.row.col.f32.bf16.bf16.f32 "
        "{%0,%1,%2,%3}, {%4,%5,%6,%7}, {%8,%9}, {%0,%1,%2,%3};"
        : "+f"(d[0]), "+f"(d[1]), "+f"(d[2]), "+f"(d[3])
        : "r"(a0), "r"(a1), "r"(a2), "r"(a3), "r"(b0), "r"(b1));
}
__device__ __forceinline__ void mma1688tf(float* d,
    uint32_t a0, uint32_t a1, uint32_t a2, uint32_t a3,
    uint32_t b0, uint32_t b1)
{
    asm volatile(
        "mma.sync.aligned.m16n8k8.row.col.f32.tf32.tf32.f32 "
        "{%0,%1,%2,%3}, {%4,%5,%6,%7}, {%8,%9}, {%0,%1,%2,%3};"
        : "+f"(d[0]), "+f"(d[1]), "+f"(d[2]), "+f"(d[3])
        : "r"(a0), "r"(a1), "r"(a2), "r"(a3), "r"(b0), "r"(b1));
}
__device__ __forceinline__ void ldsm4(uint32_t* r, uint32_t addr) {
    asm volatile("ldmatrix.sync.aligned.m8n8.x4.shared.b16 {%0,%1,%2,%3}, [%4];"
        : "=r"(r[0]), "=r"(r[1]), "=r"(r[2]), "=r"(r[3]) : "r"(addr));
}
__device__ __forceinline__ uint32_t packbf(float lo, float hi) {
    __nv_bfloat162 p = __floats2bfloat162_rn(lo, hi);
    return *(uint32_t*)&p;
}
__device__ __forceinline__ float ex2f(float x) {
    float r; asm("ex2.approx.ftz.f32 %0, %1;" : "=f"(r) : "f"(x)); return r;
}
__device__ __forceinline__ float bflo(uint32_t u) { return __uint_as_float(u << 16); }
__device__ __forceinline__ float bfhi(uint32_t u) { return __uint_as_float(u & 0xffff0000u); }
__device__ __forceinline__ uint32_t f2tf32(float x) {
    uint32_t r; asm("cvt.rna.tf32.f32 %0, %1;" : "=r"(r) : "f"(x)); return r;
}
__device__ __forceinline__ void cpa16(uint32_t s, const void* g) {
    asm volatile("{ .reg .u64 gg; cvta.to.global.u64 gg, %1; "
                 "cp.async.cg.shared.global [%0], [gg], 16; }" :: "r"(s), "l"(g));
}
__device__ __forceinline__ void cpa4(uint32_t s, const void* g) {
    asm volatile("{ .reg .u64 gg; cvta.to.global.u64 gg, %1; "
                 "cp.async.ca.shared.global [%0], [gg], 4; }" :: "r"(s), "l"(g));
}
#define CP_COMMIT() asm volatile("cp.async.commit_group;" ::: "memory")
#define CP_WAIT1()  asm volatile("cp.async.wait_group 1;" ::: "memory")
#define CP_WAIT0()  asm volatile("cp.async.wait_group 0;" ::: "memory")

// ---------------- tf32 GEMM for proj_in: xf = W_in @ x, + xft bf16 ---------
__global__ __launch_bounds__(128) void gemm_in(
    const float* __restrict__ W, const float* __restrict__ X)
{
    __shared__ uint32_t As[64 * 68];
    __shared__ uint32_t Bs[64 * 68];

    const int t = threadIdx.x;
    const int lane = t & 31, wid = t >> 5;
    const int gid = lane >> 2, kl = lane & 3, q2 = kl * 2;
    const int mblk = blockIdx.y * 64, nblk = blockIdx.x * 64, b = blockIdx.z;
    const int wm = wid * 16;

    float acc[8][4];
#pragma unroll
    for (int nt = 0; nt < 8; nt++)
#pragma unroll
        for (int j = 0; j < 4; j++) acc[nt][j] = 0.f;

    for (int ks = 0; ks < 128; ks += 64) {
        __syncthreads();
#pragma unroll
        for (int i = 0; i < 8; i++) {
            int idx = t + i * 128;
            int row = idx >> 4, c4 = (idx & 15) * 4;
            float4 av = *(const float4*)(W + (size_t)(mblk + row) * 128 + ks + c4);
            As[row * 68 + c4 + 0] = f2tf32(av.x);
            As[row * 68 + c4 + 1] = f2tf32(av.y);
            As[row * 68 + c4 + 2] = f2tf32(av.z);
            As[row * 68 + c4 + 3] = f2tf32(av.w);
            float4 bv = *(const float4*)(X + (size_t)b * 131072 +
                                         (size_t)(ks + row) * NTOK + nblk + c4);
            Bs[(c4 + 0) * 68 + row] = f2tf32(bv.x);
            Bs[(c4 + 1) * 68 + row] = f2tf32(bv.y);
            Bs[(c4 + 2) * 68 + row] = f2tf32(bv.z);
            Bs[(c4 + 3) * 68 + row] = f2tf32(bv.w);
        }
        __syncthreads();
#pragma unroll
        for (int kk = 0; kk < 64; kk += 8) {
            uint32_t a0 = As[(wm + gid) * 68 + kk + kl];
            uint32_t a1 = As[(wm + gid + 8) * 68 + kk + kl];
            uint32_t a2 = As[(wm + gid) * 68 + kk + kl + 4];
            uint32_t a3 = As[(wm + gid + 8) * 68 + kk + kl + 4];
#pragma unroll
            for (int nt = 0; nt < 8; nt++) {
                uint32_t b0 = Bs[(nt * 8 + gid) * 68 + kk + kl];
                uint32_t b1 = Bs[(nt * 8 + gid) * 68 + kk + kl + 4];
                mma1688tf(acc[nt], a0, a1, a2, a3, b0, b1);
            }
        }
    }

    float* xfb = g_xf + (size_t)b * C2D * NTOK;
    __nv_bfloat16* xtb = g_xft + (size_t)b * NTOK * C2D;
    const int r0 = mblk + wm + gid;
#pragma unroll
    for (int nt = 0; nt < 8; nt++) {
        int col = nblk + nt * 8 + q2;
        *(float2*)(xfb + (size_t)r0 * NTOK + col) =
            make_float2(acc[nt][0], acc[nt][1]);
        *(float2*)(xfb + (size_t)(r0 + 8) * NTOK + col) =
            make_float2(acc[nt][2], acc[nt][3]);
        xtb[(size_t)col * C2D + r0]           = __float2bfloat16(acc[nt][0]);
        xtb[(size_t)(col + 1) * C2D + r0]     = __float2bfloat16(acc[nt][1]);
        xtb[(size_t)col * C2D + r0 + 8]       = __float2bfloat16(acc[nt][2]);
        xtb[(size_t)(col + 1) * C2D + r0 + 8] = __float2bfloat16(acc[nt][3]);
    }
}

// ---------------- bf16 GEMM (templated warp-tile height) -------------------
#define GK   256
#define GCH  128
#define GLD2 136
#define GH_SMEM_M(MI) ((64 * (MI) + 64) * GLD2 * 2)
template<int MI>
__global__ __launch_bounds__(128) void gemm_h(
    const float* __restrict__ Af, const __nv_bfloat16* __restrict__ Xt,
    float* __restrict__ C, const float* __restrict__ add_src, int mode)
{
    extern __shared__ __nv_bfloat16 gh[];
    __nv_bfloat16* As = gh;                       // [64*MI][GLD2]
    __nv_bfloat16* Bs = gh + 64 * MI * GLD2;      // [64][GLD2]

    const int t = threadIdx.x;
    const int lane = t & 31, wid = t >> 5;
    const int gid = lane >> 2, q2 = (lane & 3) * 2;
    const int lrow = lane & 7, lmi = lane >> 3;
    const int mblk = blockIdx.y * 64 * MI, nblk = blockIdx.x * 64, b = blockIdx.z;
    const int wm = wid * 16 * MI;

    const __nv_bfloat16* Xb = Xt + ((size_t)b * NTOK + nblk) * GK;
    const uint32_t as_b = smem_u32(As);
    const uint32_t bs_b = smem_u32(Bs);
    const uint32_t a_addr0 = as_b + 2 * ((wm + ((lmi & 1) << 3) + lrow) * GLD2 + ((lmi >> 1) << 3));
    const uint32_t a_addr1 = a_addr0 + 2 * (16 * GLD2);
    const uint32_t b_row   = (uint32_t)(((lmi >> 1) << 3) + lrow) * GLD2 + ((lmi & 1) << 3);

    float acc[MI][8][4];
#pragma unroll
    for (int mi = 0; mi < MI; mi++)
#pragma unroll
        for (int nt = 0; nt < 8; nt++)
#pragma unroll
            for (int j = 0; j < 4; j++) acc[mi][nt][j] = 0.f;

#pragma unroll
    for (int kc = 0; kc < 2; kc++) {
        __syncthreads();
        const float* Ab = Af + (size_t)mblk * GK + kc * GCH;
        const __nv_bfloat16* Bb = Xb + kc * GCH;
#pragma unroll
        for (int i = 0; i < 8 * MI; i++) {
            int idx = t + i * 128;
            int row = idx >> 4, q = (idx & 15) * 8;
            float4 v0 = *(const float4*)(Ab + (size_t)row * GK + q);
            float4 v1 = *(const float4*)(Ab + (size_t)row * GK + q + 4);
            uint4 w;
            w.x = packbf(v0.x, v0.y); w.y = packbf(v0.z, v0.w);
            w.z = packbf(v1.x, v1.y); w.w = packbf(v1.z, v1.w);
            *(uint4*)(As + row * GLD2 + q) = w;
        }
#pragma unroll
        for (int i = 0; i < 8; i++) {
            int idx = t + i * 128;
            int row = idx >> 4, q = (idx & 15) * 8;
            *(uint4*)(Bs + row * GLD2 + q) = *(const uint4*)(Bb + (size_t)row * GK + q);
        }
        __syncthreads();
#pragma unroll
        for (int kt = 0; kt < GCH / 16; kt++) {
            const int ka = kt * 16;
            uint32_t ar[MI][4];
            ldsm4(ar[0], a_addr0 + 2 * ka);
            if (MI == 2) ldsm4(ar[MI - 1], a_addr1 + 2 * ka);
#pragma unroll
            for (int np = 0; np < 4; np++) {
                uint32_t br[4];
                ldsm4(br, bs_b + 2 * (b_row + (np * 16) * GLD2 + ka));
#pragma unroll
                for (int mi = 0; mi < MI; mi++) {
                    mma16816(acc[mi][2 * np],     ar[mi][0], ar[mi][1], ar[mi][2], ar[mi][3], br[0], br[1]);
                    mma16816(acc[mi][2 * np + 1], ar[mi][0], ar[mi][1], ar[mi][2], ar[mi][3], br[2], br[3]);
                }
            }
        }
    }

#pragma unroll
    for (int mi = 0; mi < MI; mi++) {
        const int r0 = mblk + wm + mi * 16 + gid;
        if (mode == 1) {
            const int sector = r0 >> 8;
            const int hh = (r0 >> 5) & 7, dd = r0 & 31;
            if (sector < 2) {
                __nv_bfloat16* base = (sector == 0 ? g_qh : g_kh) +
                    (size_t)(b * NHEAD + hh) * NTOK * DHEAD;
#pragma unroll
                for (int nt = 0; nt < 8; nt++) {
                    int n = nblk + nt * 8 + q2;
                    base[(size_t)n * DHEAD + dd]           = __float2bfloat16(acc[mi][nt][0]);
                    base[(size_t)(n + 1) * DHEAD + dd]     = __float2bfloat16(acc[mi][nt][1]);
                    base[(size_t)n * DHEAD + dd + 8]       = __float2bfloat16(acc[mi][nt][2]);
                    base[(size_t)(n + 1) * DHEAD + dd + 8] = __float2bfloat16(acc[mi][nt][3]);
                }
            } else {
                __nv_bfloat16* vb = g_vh + (size_t)(b * NHEAD + hh) * DHEAD * NTOK;
#pragma unroll
                for (int nt = 0; nt < 8; nt++) {
                    int n = nblk + nt * 8 + q2;
                    *(uint32_t*)(vb + (size_t)dd * NTOK + n)       = packbf(acc[mi][nt][0], acc[mi][nt][1]);
                    *(uint32_t*)(vb + (size_t)(dd + 8) * NTOK + n) = packbf(acc[mi][nt][2], acc[mi][nt][3]);
                }
            }
        } else {
            float* Cb = C + (size_t)b * C2D * NTOK;
            const float* ab = add_src + (size_t)b * C2D * NTOK;
#pragma unroll
            for (int nt = 0; nt < 8; nt++) {
                int col = nblk + nt * 8 + q2;
                float2 a0 = *(const float2*)(ab + (size_t)r0 * NTOK + col);
                float2 a1 = *(const float2*)(ab + (size_t)(r0 + 8) * NTOK + col);
                *(float2*)(Cb + (size_t)r0 * NTOK + col) =
                    make_float2(acc[mi][nt][0] + a0.x, acc[mi][nt][1] + a0.y);
                *(float2*)(Cb + (size_t)(r0 + 8) * NTOK + col) =
                    make_float2(acc[mi][nt][2] + a1.x, acc[mi][nt][3] + a1.y);
            }
        }
    }
}

// ---------------- attention (Q pre-scaled by pn*SCALE*log2e) ---------------
#define ROWT 64
#define KS_LD 40
#define VT_LD 136
#define KS_BYTES (128 * KS_LD * 2)
#define VT_BYTES (DHEAD * VT_LD * 2)

__global__ void __launch_bounds__(128, 4) attn_kernel()
{
    __shared__ __align__(16) __nv_bfloat16 Ks[2][128 * KS_LD];
    __shared__ __align__(16) __nv_bfloat16 Vt[2][DHEAD * VT_LD];
    __shared__ float pm_s[2][KCL * 128];

    const int t    = threadIdx.x;
    const int wid  = t >> 5;
    const int lane = t & 31;
    const int gid  = lane >> 2;
    const int q2   = (lane & 3) * 2;
    const int lrow = lane & 7, lmi = lane >> 3;

    const int n0 = blockIdx.x * ROWT;
    const int h  = blockIdx.y;
    const int b  = blockIdx.z;

    const __nv_bfloat16* qh = g_qh + (size_t)(b * NHEAD + h) * NTOK * DHEAD;
    const __nv_bfloat16* kh = g_kh + (size_t)(b * NHEAD + h) * NTOK * DHEAD;
    const __nv_bfloat16* vh = g_vh + (size_t)(b * NHEAD + h) * DHEAD * NTOK;
    const float* pbase = g_prob + (size_t)b * KCL * NTOK;

    const int n_g = n0 + wid * 16 + gid;

    const uint32_t ks_u = smem_u32(Ks);
    const uint32_t vt_u = smem_u32(Vt);
    const uint32_t pm_u = smem_u32(pm_s);

    const int st_krow = t >> 2, st_kq = (t & 3) * 8;
    const int st_vd   = t >> 4, st_vq = (t & 15) * 8;
    auto stage = [&](int mt, int bufi) {
        uint32_t kb = ks_u + bufi * KS_BYTES;
        uint32_t vb = vt_u + bufi * VT_BYTES;
#pragma unroll
        for (int i = 0; i < 4; i++) {
            int row = st_krow + i * 32;
            cpa16(kb + (uint32_t)(row * KS_LD + st_kq) * 2,
                  kh + (size_t)(mt + row) * DHEAD + st_kq);
        }
#pragma unroll
        for (int i = 0; i < 4; i++) {
            int d = st_vd + i * 8;
            cpa16(vb + (uint32_t)(d * VT_LD + st_vq) * 2,
                  vh + (size_t)d * NTOK + mt + st_vq);
        }
#pragma unroll
        for (int i = 0; i < 3; i++) {
            int idx = t + i * 128;
            int cl = idx >> 7, m = idx & 127;
            cpa4(pm_u + (uint32_t)(bufi * KCL * 128 + cl * 128 + m) * 4,
                 pbase + (size_t)cl * NTOK + mt + m);
        }
    };

    // ---- Q fragments pre-scaled per cluster by pn*EXPSC ----
    uint32_t qs[KCL][2][4];
    {
        uint32_t qa[2][4];
#pragma unroll
        for (int kt = 0; kt < 2; kt++) {
            int d0 = kt * 16 + q2;
            qa[kt][0] = *(const uint32_t*)(qh + (size_t)n_g * DHEAD + d0);
            qa[kt][1] = *(const uint32_t*)(qh + (size_t)(n_g + 8) * DHEAD + d0);
            qa[kt][2] = *(const uint32_t*)(qh + (size_t)n_g * DHEAD + d0 + 8);
            qa[kt][3] = *(const uint32_t*)(qh + (size_t)(n_g + 8) * DHEAD + d0 + 8);
        }
#pragma unroll
        for (int i = 0; i < KCL; i++) {
            float w0 = pbase[i * NTOK + n_g] * EXPSC;
            float w1 = pbase[i * NTOK + n_g + 8] * EXPSC;
#pragma unroll
            for (int kt = 0; kt < 2; kt++) {
                qs[i][kt][0] = packbf(bflo(qa[kt][0]) * w0, bfhi(qa[kt][0]) * w0);
                qs[i][kt][1] = packbf(bflo(qa[kt][1]) * w1, bfhi(qa[kt][1]) * w1);
                qs[i][kt][2] = packbf(bflo(qa[kt][2]) * w0, bfhi(qa[kt][2]) * w0);
                qs[i][kt][3] = packbf(bflo(qa[kt][3]) * w1, bfhi(qa[kt][3]) * w1);
            }
        }
    }

    float oacc[KCL][4][4];
    float lacc[KCL][2];
#pragma unroll
    for (int i = 0; i < KCL; i++) {
        lacc[i][0] = lacc[i][1] = 0.f;
#pragma unroll
        for (int dt = 0; dt < 4; dt++)
#pragma unroll
            for (int j = 0; j < 4; j++) oacc[i][dt][j] = 0.f;
    }

    const uint32_t k_off = (uint32_t)lrow * KS_LD + lmi * 8;
    const uint32_t v_off = (uint32_t)(((lmi >> 1) << 3) + lrow) * VT_LD + ((lmi & 1) << 3);

    stage(0, 0);
    CP_COMMIT();

    int buf = 0;
    for (int it = 0; it < 8; it++) {
        if (it) __syncthreads();
        if (it < 7) { stage((it + 1) * 128, buf ^ 1); CP_COMMIT(); CP_WAIT1(); }
        else CP_WAIT0();
        __syncthreads();

        const uint32_t ks_b = ks_u + buf * KS_BYTES;
        const uint32_t vt_b = vt_u + buf * VT_BYTES;
        const float* pmb = pm_s[buf];

#pragma unroll
        for (int chunk = 0; chunk < 4; chunk++) {
            const int c0 = chunk * 32;
            // S_i fragments: 3 clusters computed from cluster-scaled Q
            float sacc[KCL][4][4];
#pragma unroll
            for (int nt = 0; nt < 4; nt++) {
                uint32_t br[4];
                ldsm4(br, ks_b + 2 * ((uint32_t)(c0 + nt * 8) * KS_LD + k_off));
#pragma unroll
                for (int i = 0; i < KCL; i++) {
                    sacc[i][nt][0] = sacc[i][nt][1] = sacc[i][nt][2] = sacc[i][nt][3] = 0.f;
                    mma16816(sacc[i][nt], qs[i][0][0], qs[i][0][1], qs[i][0][2], qs[i][0][3], br[0], br[1]);
                    mma16816(sacc[i][nt], qs[i][1][0], qs[i][1][1], qs[i][1][2], qs[i][1][3], br[2], br[3]);
                }
            }

#pragma unroll
            for (int s = 0; s < 2; s++) {
                uint32_t vr[2][4];
#pragma unroll
                for (int dp = 0; dp < 2; dp++)
                    ldsm4(vr[dp], vt_b + 2 * ((uint32_t)(dp * 16) * VT_LD + v_off
                                             + (uint32_t)(c0 + 16 * s)));
                const int j0 = 2 * s, j1 = 2 * s + 1;
#pragma unroll
                for (int i = 0; i < KCL; i++) {
                    const float* pc = pmb + i * 128 + c0 + 16 * s;
                    float pm00 = pc[q2],     pm01 = pc[q2 + 1];
                    float pm10 = pc[q2 + 8], pm11 = pc[q2 + 9];
                    float e00 = ex2f(sacc[i][j0][0] * pm00);
                    float e01 = ex2f(sacc[i][j0][1] * pm01);
                    float e02 = ex2f(sacc[i][j0][2] * pm00);
                    float e03 = ex2f(sacc[i][j0][3] * pm01);
                    float e10 = ex2f(sacc[i][j1][0] * pm10);
                    float e11 = ex2f(sacc[i][j1][1] * pm11);
                    float e12 = ex2f(sacc[i][j1][2] * pm10);
                    float e13 = ex2f(sacc[i][j1][3] * pm11);
                    lacc[i][0] += e00 + e01 + e10 + e11;
                    lacc[i][1] += e02 + e03 + e12 + e13;
                    uint32_t ra0 = packbf(e00 * pm00, e01 * pm01);
                    uint32_t ra1 = packbf(e02 * pm00, e03 * pm01);
                    uint32_t ra2 = packbf(e10 * pm10, e11 * pm11);
                    uint32_t ra3 = packbf(e12 * pm10, e13 * pm11);
#pragma unroll
                    for (int dt = 0; dt < 4; dt++)
                        mma16816(oacc[i][dt], ra0, ra1, ra2, ra3,
                                 vr[dt >> 1][(dt & 1) * 2],
                                 vr[dt >> 1][(dt & 1) * 2 + 1]);
                }
            }
        }
        buf ^= 1;
    }

    float inv0[KCL], inv1[KCL];
#pragma unroll
    for (int i = 0; i < KCL; i++) {
        float l0 = lacc[i][0], l1 = lacc[i][1];
        l0 += __shfl_xor_sync(0xffffffffu, l0, 1);
        l0 += __shfl_xor_sync(0xffffffffu, l0, 2);
        l1 += __shfl_xor_sync(0xffffffffu, l1, 1);
        l1 += __shfl_xor_sync(0xffffffffu, l1, 2);
        inv0[i] = __fdividef(1.f, 3.f * l0);
        inv1[i] = __fdividef(1.f, 3.f * l1);
    }

    __nv_bfloat16* ob0 = g_attt + ((size_t)b * NTOK + n_g)     * C2D + h * DHEAD;
    __nv_bfloat16* ob1 = g_attt + ((size_t)b * NTOK + n_g + 8) * C2D + h * DHEAD;
#pragma unroll
    for (int dt = 0; dt < 4; dt++) {
        int d0 = dt * 8 + q2;
        float o00 = 0.f, o01 = 0.f, o10 = 0.f, o11 = 0.f;
#pragma unroll
        for (int i = 0; i < KCL; i++) {
            o00 += oacc[i][dt][0] * inv0[i];
            o01 += oacc[i][dt][1] * inv0[i];
            o10 += oacc[i][dt][2] * inv1[i];
            o11 += oacc[i][dt][3] * inv1[i];
        }
        *(uint32_t*)(ob0 + d0) = packbf(o00, o01);
        *(uint32_t*)(ob1 + d0) = packbf(o10, o11);
    }
}

// ---------------- cluster probs --------------------------------------------
__global__ __launch_bounds__(256) void prob_kernel(
    const float* __restrict__ Wc, const float* __restrict__ bc)
{
    __shared__ float W[KCL * C2D];
    __shared__ float bias[KCL];
    const int t = threadIdx.x;
    for (int i = t; i < KCL * C2D; i += 256) W[i] = Wc[i];
    if (t < KCL) bias[t] = bc[t];
    __syncthreads();

    const int gidx = blockIdx.x * 256 + t;
    const int tok = gidx >> 2;
    const int p   = t & 3;
    const int b = tok >> 10, n = tok & 1023;

    const __nv_bfloat16* xp = g_xft + ((size_t)(b * NTOK + n)) * C2D + p * 64;
    const float* W0 = W + p * 64;
    float l0 = 0.f, l1 = 0.f, l2 = 0.f;
#pragma unroll
    for (int j = 0; j < 8; j++) {
        uint4 v = *(const uint4*)(xp + j * 8);
        const float* w = W0 + j * 8;
        float x0 = bflo(v.x), x1 = bfhi(v.x);
        float x2 = bflo(v.y), x3 = bfhi(v.y);
        float x4 = bflo(v.z), x5 = bfhi(v.z);
        float x6 = bflo(v.w), x7 = bfhi(v.w);
        l0 = fmaf(w[0], x0, l0); l0 = fmaf(w[1], x1, l0);
        l0 = fmaf(w[2], x2, l0); l0 = fmaf(w[3], x3, l0);
        l0 = fmaf(w[4], x4, l0); l0 = fmaf(w[5], x5, l0);
        l0 = fmaf(w[6], x6, l0); l0 = fmaf(w[7], x7, l0);
        l1 = fmaf(w[C2D + 0], x0, l1); l1 = fmaf(w[C2D + 1], x1, l1);
        l1 = fmaf(w[C2D + 2], x2, l1); l1 = fmaf(w[C2D + 3], x3, l1);
        l1 = fmaf(w[C2D + 4], x4, l1); l1 = fmaf(w[C2D + 5], x5, l1);
        l1 = fmaf(w[C2D + 6], x6, l1); l1 = fmaf(w[C2D + 7], x7, l1);
        l2 = fmaf(w[2 * C2D + 0], x0, l2); l2 = fmaf(w[2 * C2D + 1], x1, l2);
        l2 = fmaf(w[2 * C2D + 2], x2, l2); l2 = fmaf(w[2 * C2D + 3], x3, l2);
        l2 = fmaf(w[2 * C2D + 4], x4, l2); l2 = fmaf(w[2 * C2D + 5], x5, l2);
        l2 = fmaf(w[2 * C2D + 6], x6, l2); l2 = fmaf(w[2 * C2D + 7], x7, l2);
    }
    l0 += __shfl_xor_sync(0xffffffffu, l0, 1);
    l0 += __shfl_xor_sync(0xffffffffu, l0, 2);
    l1 += __shfl_xor_sync(0xffffffffu, l1, 1);
    l1 += __shfl_xor_sync(0xffffffffu, l1, 2);
    l2 += __shfl_xor_sync(0xffffffffu, l2, 1);
    l2 += __shfl_xor_sync(0xffffffffu, l2, 2);

    if (p == 0) {
        l0 += bias[0]; l1 += bias[1]; l2 += bias[2];
        float mx = fmaxf(l0, fmaxf(l1, l2));
        float e0 = __expf(l0 - mx), e1 = __expf(l1 - mx), e2 = __expf(l2 - mx);
        float inv = 1.f / (e0 + e1 + e2);
        float* pb = g_prob + (size_t)b * KCL * NTOK + n;
        pb[0]        = e0 * inv;
        pb[NTOK]     = e1 * inv;
        pb[2 * NTOK] = e2 * inv;
    }
}

// ---------------- launch ---------------------------------------------------
extern "C" void kernel_launch(void* const* d_in, const int* in_sizes, int n_in,
                              void* d_out, int out_size)
{
    const float* x      = (const float*)d_in[0];
    const float* W_in   = (const float*)d_in[1];
    const float* Wc     = (const float*)d_in[2];
    const float* bc     = (const float*)d_in[3];
    const float* W_qkv  = (const float*)d_in[4];
    const float* W_proj = (const float*)d_in[5];
    float* out = (float*)d_out;

    float* xf;
    __nv_bfloat16 *xft, *attt;
    cudaGetSymbolAddress((void**)&xf,   g_xf);
    cudaGetSymbolAddress((void**)&xft,  g_xft);
    cudaGetSymbolAddress((void**)&attt, g_attt);

    cudaFuncSetAttribute(gemm_h<2>,
        cudaFuncAttributeMaxDynamicSharedMemorySize, GH_SMEM_M(2));
    cudaFuncSetAttribute(gemm_h<1>,
        cudaFuncAttributeMaxDynamicSharedMemorySize, GH_SMEM_M(1));

    // 1) xf = W_in @ x (tf32 tensor) + fused bf16 transpose to xft
    gemm_in<<<dim3(16, 4, BDIM), 128>>>(W_in, x);
    // 2) cluster probs (from xft)
    prob_kernel<<<(BDIM * NTOK * 4) / 256, 256>>>(Wc, bc);
    // 3) qkv GEMM (wide 128-row tile), fused q/k/v epilogue
    gemm_h<2><<<dim3(16, 6, BDIM), 128, GH_SMEM_M(2)>>>(W_qkv, xft, nullptr, nullptr, 1);
    // 4) clustered attention (Q pre-scaled, single-mul exp args)
    attn_kernel<<<dim3(NTOK / ROWT, NHEAD, BDIM), 128>>>();
    // 5) out = W_proj @ att + xf (64-row tile for occupancy)
    gemm_h<1><<<dim3(16, 4, BDIM), 128, GH_SMEM_M(1)>>>(W_proj, attt, out, xf, 0);
}